// round 10
// baseline (speedup 1.0000x reference)
#include <cuda_runtime.h>
#include <cuda_bf16.h>

// TD(lambda) backward scan — warp-per-row, 4-elem micro-segments + warp scan.
// R9: (a) REVERT cp.async + streaming hints (R6 regression);
//     (b) drop smem v-staging: direct scalar LDGs of the misaligned values
//         segments touch the same unique sectors, so staging bought nothing;
//     (c) hoist tanh(lambda)/tanh(gamma) into a one-shot prep kernel writing
//         a __device__ table -> main kernel has NO smem, NO syncs, NO MUFU.
//
// ret_t = a_t*ret_{t+1} + b_t;  a_t = gamma*(1-d_t)*lam_t,
//                               b_t = r_t + gamma*(1-d_t)*(1-lam_t)*v_{t+1}

#define B_TOT 32768
#define S_LEN 512
#define EPS_F 1e-8f

static constexpr int WPB = 8;   // warps (rows) per block -> 256 threads

// lambda table [0..511], gamma at [512] (+pad to keep 16B-aligned size)
__device__ __align__(16) float g_lam[S_LEN + 4];

__global__ void prep_kernel(const float* __restrict__ raw_gamma,
                            const float* __restrict__ raw_lambd)
{
    const int i = threadIdx.x;
    g_lam[i] = fmaxf(tanhf(raw_lambd[i]), EPS_F);
    if (i == 0)
        g_lam[S_LEN] = fmaxf(tanhf(raw_gamma[0]), EPS_F);
}

__global__ __launch_bounds__(WPB * 32)
void gamma_lambda_wscan3_kernel(
    const float* __restrict__ values,    // [B, S+1]
    const float* __restrict__ rewards,   // [B, S]
    const float* __restrict__ dones,     // [B, S]
    float* __restrict__ out)             // [B, S]
{
    const int tid  = threadIdx.x;
    const int lane = tid & 31;
    const int wid  = tid >> 5;

    const int row = blockIdx.x * WPB + wid;          // exact: 4096*8 = 32768
    const float* vrow = values  + (size_t)row * (S_LEN + 1);
    const float* rrow = rewards + (size_t)row * S_LEN;
    const float* drow = dones   + (size_t)row * S_LEN;
    float*       orow = out     + (size_t)row * S_LEN;

    const float gamma = __ldg(&g_lam[S_LEN]);

    // ---- per-chunk: coalesced loads, build (a,b), compose segment ----
    float a[4][4], b[4][4];
    float A[4], Bv[4];
#pragma unroll
    for (int c = 0; c < 4; c++) {
        const int base = c * 128 + lane * 4;
        const float4 r4 = __ldg((const float4*)(rrow + base));
        const float4 d4 = __ldg((const float4*)(drow + base));
        const float4 l4 = __ldg((const float4*)(g_lam + base));
        // values row is odd-length (513) -> 4B-aligned only: scalar LDGs.
        // A warp's 4 requests cover the same 4 cache lines (no extra sectors).
        float vv[4];
#pragma unroll
        for (int j = 0; j < 4; j++)
            vv[j] = __ldg(vrow + 1 + base + j);
        const float rr[4] = {r4.x, r4.y, r4.z, r4.w};
        const float dd[4] = {d4.x, d4.y, d4.z, d4.w};
        const float ll[4] = {l4.x, l4.y, l4.z, l4.w};
        float Ac = 1.0f, Bc = 0.0f;
#pragma unroll
        for (int j = 3; j >= 0; --j) {
            const float gd = gamma - gamma * dd[j];          // gamma*(1-d)
            const float aj = gd * ll[j];
            const float bj = fmaf(gd - aj, vv[j], rr[j]);    // r + gd*(1-lam)*v
            a[c][j] = aj; b[c][j] = bj;
            Bc = fmaf(aj, Bc, bj);
            Ac = aj * Ac;
        }
        A[c] = Ac; Bv[c] = Bc;
    }

    // ---- 4 independent warp suffix-inclusive scans ----
#pragma unroll
    for (int off = 1; off < 32; off <<= 1) {
#pragma unroll
        for (int c = 0; c < 4; c++) {
            const float A2 = __shfl_down_sync(0xFFFFFFFFu, A[c],  off);
            const float B2 = __shfl_down_sync(0xFFFFFFFFu, Bv[c], off);
            if (lane + off < 32) {
                Bv[c] = fmaf(A[c], B2, Bv[c]);
                A[c]  = A[c] * A2;
            }
        }
    }

    // chunk totals (lane 0 holds full-chunk map)
    float TA[4], TB[4];
#pragma unroll
    for (int c = 0; c < 4; c++) {
        TA[c] = __shfl_sync(0xFFFFFFFFu, A[c],  0);
        TB[c] = __shfl_sync(0xFFFFFFFFu, Bv[c], 0);
    }

    // exclusive per-lane suffix within each chunk
    float Ae[4], Be[4];
#pragma unroll
    for (int c = 0; c < 4; c++) {
        Ae[c] = __shfl_down_sync(0xFFFFFFFFu, A[c],  1);
        Be[c] = __shfl_down_sync(0xFFFFFFFFu, Bv[c], 1);
        if (lane == 31) { Ae[c] = 1.0f; Be[c] = 0.0f; }
    }

    // ---- chunk boundaries: x[c] = ret_{128(c+1)}; x[3] = values[b,S] ----
    const float v_init = __ldg(vrow + S_LEN);   // broadcast load (1 sector)
    float x[4];
    x[3] = v_init;
    x[2] = fmaf(TA[3], x[3], TB[3]);
    x[1] = fmaf(TA[2], x[2], TB[2]);
    x[0] = fmaf(TA[1], x[1], TB[1]);

    // ---- replay, coalesced float4 stores ----
#pragma unroll
    for (int c = 0; c < 4; c++) {
        const float y  = fmaf(Ae[c], x[c], Be[c]);
        const float o3 = fmaf(a[c][3], y,  b[c][3]);
        const float o2 = fmaf(a[c][2], o3, b[c][2]);
        const float o1 = fmaf(a[c][1], o2, b[c][1]);
        const float o0 = fmaf(a[c][0], o1, b[c][0]);
        *(float4*)(orow + c * 128 + lane * 4) = make_float4(o0, o1, o2, o3);
    }
}

extern "C" void kernel_launch(void* const* d_in, const int* in_sizes, int n_in,
                              void* d_out, int out_size)
{
    const float* values    = (const float*)d_in[0];
    const float* rewards   = (const float*)d_in[1];
    const float* dones     = (const float*)d_in[2];
    const float* raw_gamma = (const float*)d_in[3];
    const float* raw_lambd = (const float*)d_in[4];
    float* out = (float*)d_out;

    prep_kernel<<<1, S_LEN>>>(raw_gamma, raw_lambd);

    const int threads = WPB * 32;          // 256
    const int blocks  = B_TOT / WPB;       // 4096
    gamma_lambda_wscan3_kernel<<<blocks, threads>>>(values, rewards, dones, out);
}

// round 12
// speedup vs baseline: 1.0440x; 1.0440x over previous
#include <cuda_runtime.h>
#include <cuda_bf16.h>

// TD(lambda) backward scan — warp-per-row, 4-elem micro-segments + warp scan.
// R10 = R5 base (smem v-staging, in-kernel tanh, plain LDG/STG) +
//   (a) snapshot-map replay: store partial composed maps P1..P3 built during
//       the backward compose instead of raw (a_j,b_j) -> 8 fewer live regs,
//       replay is 4 independent FMAs (no serial chain);
//   (b) __launch_bounds__(256,5): cap regs ~51 -> 5 blocks/SM occupancy.
//
// ret_t = a_t*ret_{t+1} + b_t;  a_t = gamma*(1-d_t)*lam_t,
//                               b_t = r_t + gamma*(1-d_t)*(1-lam_t)*v_{t+1}

#define B_TOT 32768
#define S_LEN 512
#define EPS_F 1e-8f

static constexpr int WPB = 8;   // warps (rows) per block -> 256 threads

__global__ __launch_bounds__(WPB * 32, 5)
void gamma_lambda_wscan4_kernel(
    const float* __restrict__ values,    // [B, S+1]
    const float* __restrict__ rewards,   // [B, S]
    const float* __restrict__ dones,     // [B, S]
    const float* __restrict__ raw_gamma, // [1]
    const float* __restrict__ raw_lambd, // [S]
    float* __restrict__ out)             // [B, S]
{
    __shared__ __align__(16) float s_lam[S_LEN];
    __shared__ __align__(16) float s_v[WPB][S_LEN];  // v_next per warp (shifted)
    __shared__ float s_gamma;

    const int tid  = threadIdx.x;
    const int lane = tid & 31;
    const int wid  = tid >> 5;

    for (int i = tid; i < S_LEN; i += WPB * 32)
        s_lam[i] = fmaxf(tanhf(raw_lambd[i]), EPS_F);
    if (tid == 0) s_gamma = fmaxf(tanhf(raw_gamma[0]), EPS_F);

    const int row = blockIdx.x * WPB + wid;          // exact: 4096*8 = 32768
    const float* vrow = values  + (size_t)row * (S_LEN + 1);
    const float* rrow = rewards + (size_t)row * S_LEN;
    const float* drow = dones   + (size_t)row * S_LEN;
    float*       orow = out     + (size_t)row * S_LEN;

    // Stage v_next shifted: s_v[i] = values[row, i+1]. Coalesced scalar LDG.
    float* __restrict__ wv = s_v[wid];
#pragma unroll
    for (int k = 0; k < 16; k++)
        wv[k * 32 + lane] = vrow[1 + k * 32 + lane];
    __syncthreads();   // covers s_lam, s_gamma, s_v

    const float gamma = s_gamma;

    // ---- per-chunk: aligned coalesced loads, build partial maps ----
    // P_j = map from my segment's RIGHT edge y to output position j:
    //   P_3 = (a3,b3); P_2 = a2 o P_3; P_1 = a1 o P_2; P_0 -> scan variable.
    float PA[4][3], PB[4][3];     // P1..P3 per chunk (index j-1)
    float A[4], Bv[4];            // P0 -> warp-scanned inclusive suffix
#pragma unroll
    for (int c = 0; c < 4; c++) {
        const int base = c * 128 + lane * 4;
        const float4 r4 = *(const float4*)(rrow  + base);
        const float4 d4 = *(const float4*)(drow  + base);
        const float4 v4 = *(const float4*)(wv    + base);   // LDS.128
        const float4 l4 = *(const float4*)(s_lam + base);
        const float rr[4] = {r4.x, r4.y, r4.z, r4.w};
        const float dd[4] = {d4.x, d4.y, d4.z, d4.w};
        const float vv[4] = {v4.x, v4.y, v4.z, v4.w};
        const float ll[4] = {l4.x, l4.y, l4.z, l4.w};
        float Ac = 1.0f, Bc = 0.0f;
#pragma unroll
        for (int j = 3; j >= 0; --j) {
            const float gd = fmaf(-gamma, dd[j], gamma);     // gamma*(1-d)
            const float aj = gd * ll[j];
            const float bj = fmaf(gd - aj, vv[j], rr[j]);    // r + gd*(1-lam)*v
            if (j == 3) { Ac = aj; Bc = bj; }
            else        { Ac = aj * Ac; Bc = fmaf(aj, Bc, bj); }
            if (j > 0)  { PA[c][j - 1] = Ac; PB[c][j - 1] = Bc; }
        }
        A[c] = Ac; Bv[c] = Bc;    // full segment map P0
    }

    // ---- 4 independent warp suffix-inclusive scans ----
#pragma unroll
    for (int off = 1; off < 32; off <<= 1) {
#pragma unroll
        for (int c = 0; c < 4; c++) {
            const float A2 = __shfl_down_sync(0xFFFFFFFFu, A[c],  off);
            const float B2 = __shfl_down_sync(0xFFFFFFFFu, Bv[c], off);
            if (lane + off < 32) {
                Bv[c] = fmaf(A[c], B2, Bv[c]);
                A[c]  = A[c] * A2;
            }
        }
    }

    // chunk totals (lane 0 holds full-chunk map)
    float TA[4], TB[4];
#pragma unroll
    for (int c = 0; c < 4; c++) {
        TA[c] = __shfl_sync(0xFFFFFFFFu, A[c],  0);
        TB[c] = __shfl_sync(0xFFFFFFFFu, Bv[c], 0);
    }

    // exclusive per-lane suffix within each chunk (lanes lane+1..31)
    float Ae[4], Be[4];
#pragma unroll
    for (int c = 0; c < 4; c++) {
        Ae[c] = __shfl_down_sync(0xFFFFFFFFu, A[c],  1);
        Be[c] = __shfl_down_sync(0xFFFFFFFFu, Bv[c], 1);
        if (lane == 31) { Ae[c] = 1.0f; Be[c] = 0.0f; }
    }

    // ---- chunk boundaries: x[c] = ret_{128(c+1)}; x[3] = values[b,S] ----
    const float v_init = wv[S_LEN - 1];   // = values[row, 512]
    float x[4];
    x[3] = v_init;
    x[2] = fmaf(TA[3], x[3], TB[3]);
    x[1] = fmaf(TA[2], x[2], TB[2]);
    x[0] = fmaf(TA[1], x[1], TB[1]);

    // ---- replay via snapshots: 4 independent FMAs per chunk ----
#pragma unroll
    for (int c = 0; c < 4; c++) {
        const float y  = fmaf(Ae[c], x[c], Be[c]);     // ret at my right edge
        const float o0 = fmaf(A[c],     x[c], Bv[c]);  // inclusive suffix
        const float o1 = fmaf(PA[c][0], y, PB[c][0]);
        const float o2 = fmaf(PA[c][1], y, PB[c][1]);
        const float o3 = fmaf(PA[c][2], y, PB[c][2]);
        *(float4*)(orow + c * 128 + lane * 4) = make_float4(o0, o1, o2, o3);
    }
}

extern "C" void kernel_launch(void* const* d_in, const int* in_sizes, int n_in,
                              void* d_out, int out_size)
{
    const float* values    = (const float*)d_in[0];
    const float* rewards   = (const float*)d_in[1];
    const float* dones     = (const float*)d_in[2];
    const float* raw_gamma = (const float*)d_in[3];
    const float* raw_lambd = (const float*)d_in[4];
    float* out = (float*)d_out;

    const int threads = WPB * 32;          // 256
    const int blocks  = B_TOT / WPB;       // 4096
    gamma_lambda_wscan4_kernel<<<blocks, threads>>>(values, rewards, dones,
                                                    raw_gamma, raw_lambd, out);
}

// round 13
// speedup vs baseline: 1.0499x; 1.0056x over previous
#include <cuda_runtime.h>
#include <cuda_bf16.h>

// TD(lambda) backward scan — PERSISTENT warp-per-row affine scan.
// R12 = R5 memory structure (smem v-staging, in-kernel tanh, plain LDG/STG)
//     + R10 snapshot-map replay (fewer live regs, independent store FMAs)
//     + persistent single-wave grid: 592 blocks (=148 SMs x 4 CTAs), each
//       warp loops rows with stride 4736. Lambda table + block barrier paid
//       once per block; steady state is barrier-free (warp-private staging,
//       __syncwarp only). Removes ~7 wave transitions + 4096x block prologue.
//
// ret_t = a_t*ret_{t+1} + b_t;  a_t = gamma*(1-d_t)*lam_t,
//                               b_t = r_t + gamma*(1-d_t)*(1-lam_t)*v_{t+1}

#define B_TOT 32768
#define S_LEN 512
#define EPS_F 1e-8f

static constexpr int WPB       = 8;            // warps per block -> 256 threads
static constexpr int N_BLOCKS  = 592;          // 148 SMs * 4 resident CTAs
static constexpr int TOT_WARPS = N_BLOCKS * WPB;  // 4736

__global__ __launch_bounds__(WPB * 32, 4)
void gamma_lambda_pscan_kernel(
    const float* __restrict__ values,    // [B, S+1]
    const float* __restrict__ rewards,   // [B, S]
    const float* __restrict__ dones,     // [B, S]
    const float* __restrict__ raw_gamma, // [1]
    const float* __restrict__ raw_lambd, // [S]
    float* __restrict__ out)             // [B, S]
{
    __shared__ __align__(16) float s_lam[S_LEN];
    __shared__ __align__(16) float s_v[WPB][S_LEN];  // v_next, warp-private
    __shared__ float s_gamma;

    const int tid  = threadIdx.x;
    const int lane = tid & 31;
    const int wid  = tid >> 5;

    // one-time block prologue
    for (int i = tid; i < S_LEN; i += WPB * 32)
        s_lam[i] = fmaxf(tanhf(raw_lambd[i]), EPS_F);
    if (tid == 0) s_gamma = fmaxf(tanhf(raw_gamma[0]), EPS_F);
    __syncthreads();

    const float gamma = s_gamma;
    float* __restrict__ wv = s_v[wid];
    const int gw0 = blockIdx.x * WPB + wid;      // global warp id, 0..4735

    for (int row = gw0; row < B_TOT; row += TOT_WARPS) {
        const float* vrow = values  + (size_t)row * (S_LEN + 1);
        const float* rrow = rewards + (size_t)row * S_LEN;
        const float* drow = dones   + (size_t)row * S_LEN;
        float*       orow = out     + (size_t)row * S_LEN;

        // stage v_next shifted: wv[i] = values[row, i+1] (coalesced)
#pragma unroll
        for (int k = 0; k < 16; k++)
            wv[k * 32 + lane] = vrow[1 + k * 32 + lane];
        __syncwarp();

        // ---- per-chunk: coalesced loads, build snapshot maps ----
        // P_j maps my segment's RIGHT edge y to output j (P_3=(a3,b3),
        // P_2=a2 o P_3, P_1=a1 o P_2); P_0 is the scan variable.
        float PA[4][3], PB[4][3];
        float A[4], Bv[4];
#pragma unroll
        for (int c = 0; c < 4; c++) {
            const int base = c * 128 + lane * 4;
            const float4 r4 = *(const float4*)(rrow  + base);
            const float4 d4 = *(const float4*)(drow  + base);
            const float4 v4 = *(const float4*)(wv    + base);   // LDS.128
            const float4 l4 = *(const float4*)(s_lam + base);
            const float rr[4] = {r4.x, r4.y, r4.z, r4.w};
            const float dd[4] = {d4.x, d4.y, d4.z, d4.w};
            const float vv[4] = {v4.x, v4.y, v4.z, v4.w};
            const float ll[4] = {l4.x, l4.y, l4.z, l4.w};
            float Ac = 1.0f, Bc = 0.0f;
#pragma unroll
            for (int j = 3; j >= 0; --j) {
                const float gd = fmaf(-gamma, dd[j], gamma);     // gamma*(1-d)
                const float aj = gd * ll[j];
                const float bj = fmaf(gd - aj, vv[j], rr[j]);    // r + gd*(1-lam)*v
                if (j == 3) { Ac = aj; Bc = bj; }
                else        { Ac = aj * Ac; Bc = fmaf(aj, Bc, bj); }
                if (j > 0)  { PA[c][j - 1] = Ac; PB[c][j - 1] = Bc; }
            }
            A[c] = Ac; Bv[c] = Bc;
        }

        // ---- 4 independent warp suffix-inclusive scans ----
#pragma unroll
        for (int off = 1; off < 32; off <<= 1) {
#pragma unroll
            for (int c = 0; c < 4; c++) {
                const float A2 = __shfl_down_sync(0xFFFFFFFFu, A[c],  off);
                const float B2 = __shfl_down_sync(0xFFFFFFFFu, Bv[c], off);
                if (lane + off < 32) {
                    Bv[c] = fmaf(A[c], B2, Bv[c]);
                    A[c]  = A[c] * A2;
                }
            }
        }

        // chunk totals + exclusive per-lane suffixes
        float TA[4], TB[4], Ae[4], Be[4];
#pragma unroll
        for (int c = 0; c < 4; c++) {
            TA[c] = __shfl_sync(0xFFFFFFFFu, A[c],  0);
            TB[c] = __shfl_sync(0xFFFFFFFFu, Bv[c], 0);
            Ae[c] = __shfl_down_sync(0xFFFFFFFFu, A[c],  1);
            Be[c] = __shfl_down_sync(0xFFFFFFFFu, Bv[c], 1);
            if (lane == 31) { Ae[c] = 1.0f; Be[c] = 0.0f; }
        }

        // chunk boundaries: x[c] = ret_{128(c+1)}; x[3] = values[b,S]
        const float v_init = wv[S_LEN - 1];
        float x[4];
        x[3] = v_init;
        x[2] = fmaf(TA[3], x[3], TB[3]);
        x[1] = fmaf(TA[2], x[2], TB[2]);
        x[0] = fmaf(TA[1], x[1], TB[1]);

        // replay via snapshots: independent FMAs, coalesced float4 stores
#pragma unroll
        for (int c = 0; c < 4; c++) {
            const float y  = fmaf(Ae[c], x[c], Be[c]);
            const float o0 = fmaf(A[c],     x[c], Bv[c]);
            const float o1 = fmaf(PA[c][0], y, PB[c][0]);
            const float o2 = fmaf(PA[c][1], y, PB[c][1]);
            const float o3 = fmaf(PA[c][2], y, PB[c][2]);
            *(float4*)(orow + c * 128 + lane * 4) = make_float4(o0, o1, o2, o3);
        }
        __syncwarp();   // all lanes done with wv before next row overwrites
    }
}

extern "C" void kernel_launch(void* const* d_in, const int* in_sizes, int n_in,
                              void* d_out, int out_size)
{
    const float* values    = (const float*)d_in[0];
    const float* rewards   = (const float*)d_in[1];
    const float* dones     = (const float*)d_in[2];
    const float* raw_gamma = (const float*)d_in[3];
    const float* raw_lambd = (const float*)d_in[4];
    float* out = (float*)d_out;

    gamma_lambda_pscan_kernel<<<N_BLOCKS, WPB * 32>>>(values, rewards, dones,
                                                      raw_gamma, raw_lambd, out);
}

// round 14
// speedup vs baseline: 1.0936x; 1.0417x over previous
#include <cuda_runtime.h>
#include <cuda_bf16.h>

// TD(lambda) backward scan — warp-per-row, 4-elem micro-segments + warp scan.
// R13 = R5 memory structure, with the block-wide sync decoupled from the
// v-staging (syncthreads only guards s_lam; s_v is warp-private under
// __syncwarp) and all 8 r/d LDG.128s hoisted ahead of the staging loop so
// the full 4KB/warp load front issues with no barrier in the middle.
// Snapshot-map replay (R10) keeps register pressure inside 64 regs.
//
// ret_t = a_t*ret_{t+1} + b_t;  a_t = gamma*(1-d_t)*lam_t,
//                               b_t = r_t + gamma*(1-d_t)*(1-lam_t)*v_{t+1}

#define B_TOT 32768
#define S_LEN 512
#define EPS_F 1e-8f

static constexpr int WPB = 8;   // warps (rows) per block -> 256 threads

__global__ __launch_bounds__(WPB * 32, 4)
void gamma_lambda_wscan5_kernel(
    const float* __restrict__ values,    // [B, S+1]
    const float* __restrict__ rewards,   // [B, S]
    const float* __restrict__ dones,     // [B, S]
    const float* __restrict__ raw_gamma, // [1]
    const float* __restrict__ raw_lambd, // [S]
    float* __restrict__ out)             // [B, S]
{
    __shared__ __align__(16) float s_lam[S_LEN];
    __shared__ __align__(16) float s_v[WPB][S_LEN];  // v_next, warp-private
    __shared__ float s_gamma;

    const int tid  = threadIdx.x;
    const int lane = tid & 31;
    const int wid  = tid >> 5;

    for (int i = tid; i < S_LEN; i += WPB * 32)
        s_lam[i] = fmaxf(tanhf(raw_lambd[i]), EPS_F);
    if (tid == 0) s_gamma = fmaxf(tanhf(raw_gamma[0]), EPS_F);
    __syncthreads();               // guards s_lam/s_gamma ONLY

    const int row = blockIdx.x * WPB + wid;          // exact: 4096*8 = 32768
    const float* vrow = values  + (size_t)row * (S_LEN + 1);
    const float* rrow = rewards + (size_t)row * S_LEN;
    const float* drow = dones   + (size_t)row * S_LEN;
    float*       orow = out     + (size_t)row * S_LEN;

    // ---- front-hoisted r/d loads: 8 x LDG.128, no barrier behind them ----
    float4 R4[4], D4[4];
#pragma unroll
    for (int c = 0; c < 4; c++) {
        const int base = c * 128 + lane * 4;
        R4[c] = *(const float4*)(rrow + base);
        D4[c] = *(const float4*)(drow + base);
    }

    // ---- stage v_next shifted: wv[i] = values[row, i+1] (coalesced) ----
    float* __restrict__ wv = s_v[wid];
#pragma unroll
    for (int k = 0; k < 16; k++)
        wv[k * 32 + lane] = vrow[1 + k * 32 + lane];
    __syncwarp();                  // warp-local: s_v is warp-private

    const float gamma = s_gamma;

    // ---- per-chunk: build snapshot maps ----
    // P_j maps my segment's RIGHT edge y to output j (P_3=(a3,b3),
    // P_2=a2 o P_3, P_1=a1 o P_2); P_0 is the scan variable.
    float PA[4][3], PB[4][3];
    float A[4], Bv[4];
#pragma unroll
    for (int c = 0; c < 4; c++) {
        const int base = c * 128 + lane * 4;
        const float4 v4 = *(const float4*)(wv    + base);   // LDS.128
        const float4 l4 = *(const float4*)(s_lam + base);
        const float rr[4] = {R4[c].x, R4[c].y, R4[c].z, R4[c].w};
        const float dd[4] = {D4[c].x, D4[c].y, D4[c].z, D4[c].w};
        const float vv[4] = {v4.x, v4.y, v4.z, v4.w};
        const float ll[4] = {l4.x, l4.y, l4.z, l4.w};
        float Ac = 1.0f, Bc = 0.0f;
#pragma unroll
        for (int j = 3; j >= 0; --j) {
            const float gd = fmaf(-gamma, dd[j], gamma);     // gamma*(1-d)
            const float aj = gd * ll[j];
            const float bj = fmaf(gd - aj, vv[j], rr[j]);    // r + gd*(1-lam)*v
            if (j == 3) { Ac = aj; Bc = bj; }
            else        { Ac = aj * Ac; Bc = fmaf(aj, Bc, bj); }
            if (j > 0)  { PA[c][j - 1] = Ac; PB[c][j - 1] = Bc; }
        }
        A[c] = Ac; Bv[c] = Bc;
    }

    // ---- 4 independent warp suffix-inclusive scans ----
#pragma unroll
    for (int off = 1; off < 32; off <<= 1) {
#pragma unroll
        for (int c = 0; c < 4; c++) {
            const float A2 = __shfl_down_sync(0xFFFFFFFFu, A[c],  off);
            const float B2 = __shfl_down_sync(0xFFFFFFFFu, Bv[c], off);
            if (lane + off < 32) {
                Bv[c] = fmaf(A[c], B2, Bv[c]);
                A[c]  = A[c] * A2;
            }
        }
    }

    // chunk totals + exclusive per-lane suffixes
    float TA[4], TB[4], Ae[4], Be[4];
#pragma unroll
    for (int c = 0; c < 4; c++) {
        TA[c] = __shfl_sync(0xFFFFFFFFu, A[c],  0);
        TB[c] = __shfl_sync(0xFFFFFFFFu, Bv[c], 0);
        Ae[c] = __shfl_down_sync(0xFFFFFFFFu, A[c],  1);
        Be[c] = __shfl_down_sync(0xFFFFFFFFu, Bv[c], 1);
        if (lane == 31) { Ae[c] = 1.0f; Be[c] = 0.0f; }
    }

    // ---- chunk boundaries: x[c] = ret_{128(c+1)}; x[3] = values[b,S] ----
    const float v_init = wv[S_LEN - 1];
    float x[4];
    x[3] = v_init;
    x[2] = fmaf(TA[3], x[3], TB[3]);
    x[1] = fmaf(TA[2], x[2], TB[2]);
    x[0] = fmaf(TA[1], x[1], TB[1]);

    // ---- replay via snapshots: independent FMAs, coalesced stores ----
#pragma unroll
    for (int c = 0; c < 4; c++) {
        const float y  = fmaf(Ae[c], x[c], Be[c]);
        const float o0 = fmaf(A[c],     x[c], Bv[c]);
        const float o1 = fmaf(PA[c][0], y, PB[c][0]);
        const float o2 = fmaf(PA[c][1], y, PB[c][1]);
        const float o3 = fmaf(PA[c][2], y, PB[c][2]);
        *(float4*)(orow + c * 128 + lane * 4) = make_float4(o0, o1, o2, o3);
    }
}

extern "C" void kernel_launch(void* const* d_in, const int* in_sizes, int n_in,
                              void* d_out, int out_size)
{
    const float* values    = (const float*)d_in[0];
    const float* rewards   = (const float*)d_in[1];
    const float* dones     = (const float*)d_in[2];
    const float* raw_gamma = (const float*)d_in[3];
    const float* raw_lambd = (const float*)d_in[4];
    float* out = (float*)d_out;

    const int threads = WPB * 32;          // 256
    const int blocks  = B_TOT / WPB;       // 4096
    gamma_lambda_wscan5_kernel<<<blocks, threads>>>(values, rewards, dones,
                                                    raw_gamma, raw_lambd, out);
}